// round 12
// baseline (speedup 1.0000x reference)
#include <cuda_runtime.h>
#include <cuda_bf16.h>
#include <cstdint>
#include <cstddef>

// TemporalAttention — persistent CTAs, bf16 mma.sync, 16-pixel tiles.
// 152 CTAs x 256 threads. Weights staged hi/lo once per CTA. Per tile:
// A (X, 128 rows = 16px x 8t) staged directly to bf16 hi/lo via shfl pairing
// (no fp32 scratch), with 16B-chunk XOR swizzle for conflict-free STS+LDSM.
// Warps 0-3: QK GEMM (m32xn128 each) + softmax (4 px/warp, in registers);
// warps 4-7: V GEMM + attn-mix. 3-term hi/lo split, fp32 accumulate.

namespace {
constexpr int kT = 8, kC = 128, kHW = 9216, kPIX = 16, kTHREADS = 256;
constexpr int kGRID = 152;
constexpr int kSA = 272;                 // row stride in bytes (136 bf16)
// smem byte offsets
constexpr int BQK_HI = 0;                // 128 x 272
constexpr int BQK_LO = 34816;
constexpr int BV_HI  = 69632;
constexpr int BV_LO  = 104448;
constexpr int A_HI   = 139264;           // 128 x 272 (aliased by outst)
constexpr int A_LO   = 174080;
constexpr int OUTS   = A_HI;             // out staging (65.7KB <= 69.6KB)
constexpr int BIAS   = 208896;           // 256 floats
constexpr int SSM    = 209920;           // 16px * 8 * 8 floats
constexpr int kSMEM  = 214016;
}

__device__ __forceinline__ uint32_t s2u(const void* p) {
    uint32_t a;
    asm("{ .reg .u64 t; cvta.to.shared.u64 t, %1; cvt.u32.u64 %0, t; }"
        : "=r"(a) : "l"(p));
    return a;
}
__device__ __forceinline__ void ldsm4(uint32_t& r0, uint32_t& r1, uint32_t& r2,
                                      uint32_t& r3, uint32_t addr) {
    asm volatile("ldmatrix.sync.aligned.m8n8.x4.shared.b16 {%0,%1,%2,%3}, [%4];"
                 : "=r"(r0), "=r"(r1), "=r"(r2), "=r"(r3) : "r"(addr));
}
__device__ __forceinline__ void mma16816(float* d, uint32_t a0, uint32_t a1,
                                         uint32_t a2, uint32_t a3,
                                         uint32_t b0, uint32_t b1) {
    asm volatile(
        "mma.sync.aligned.m16n8k16.row.col.f32.bf16.bf16.f32 "
        "{%0,%1,%2,%3}, {%4,%5,%6,%7}, {%8,%9}, {%0,%1,%2,%3};"
        : "+f"(d[0]), "+f"(d[1]), "+f"(d[2]), "+f"(d[3])
        : "r"(a0), "r"(a1), "r"(a2), "r"(a3), "r"(b0), "r"(b1));
}
__device__ __forceinline__ void split2(float v0, float v1, uint32_t& hw,
                                       uint32_t& lw) {
    __nv_bfloat16 h0 = __float2bfloat16(v0), h1 = __float2bfloat16(v1);
    float r0 = v0 - __bfloat162float(h0), r1 = v1 - __bfloat162float(h1);
    __nv_bfloat16 l0 = __float2bfloat16(r0), l1 = __float2bfloat16(r1);
    hw = ((uint32_t)__bfloat16_as_ushort(h1) << 16) | __bfloat16_as_ushort(h0);
    lw = ((uint32_t)__bfloat16_as_ushort(l1) << 16) | __bfloat16_as_ushort(l0);
}

// 32(m: rows gw*32..+31) x 128(n) x 128(k) 3-term split GEMM.
// A region uses chunk-XOR swizzle: 16B chunk ch at row m lives at ch ^ ((m>>3)&7).
__device__ __forceinline__ void do_gemm32(uint32_t aHi, uint32_t aLo,
                                          uint32_t bHi, uint32_t bLo,
                                          int lane, int gw, float d[2][16][4]) {
#pragma unroll
    for (int mb = 0; mb < 2; ++mb)
#pragma unroll
        for (int nt = 0; nt < 16; ++nt)
#pragma unroll
            for (int r = 0; r < 4; ++r) d[mb][nt][r] = 0.f;

    const int l15 = lane & 15, lh = lane >> 4;
    uint32_t rowo[2], x7[2];
#pragma unroll
    for (int mb = 0; mb < 2; ++mb) {
        int m = gw * 32 + mb * 16 + l15;
        rowo[mb] = (uint32_t)m * kSA;
        x7[mb] = (uint32_t)((m >> 3) & 7);
    }
    const int bro = (lane & 7) + (((lane >> 4) & 1) * 8);
    const uint32_t bkh = (uint32_t)(((lane >> 3) & 1) * 16);

#pragma unroll
    for (int ks = 0; ks < 8; ++ks) {
        uint32_t ah[2][4], al[2][4];
#pragma unroll
        for (int mb = 0; mb < 2; ++mb) {
            uint32_t ao = rowo[mb] + ((((uint32_t)(ks * 2) + lh) ^ x7[mb]) << 4);
            ldsm4(ah[mb][0], ah[mb][1], ah[mb][2], ah[mb][3], aHi + ao);
            ldsm4(al[mb][0], al[mb][1], al[mb][2], al[mb][3], aLo + ao);
        }
#pragma unroll
        for (int ntp = 0; ntp < 8; ++ntp) {
            uint32_t bo = (uint32_t)(ntp * 16 + bro) * kSA + ks * 32 + bkh;
            uint32_t h0, h1, h2, h3, l0, l1, l2, l3;
            ldsm4(h0, h1, h2, h3, bHi + bo);
            ldsm4(l0, l1, l2, l3, bLo + bo);
#pragma unroll
            for (int mb = 0; mb < 2; ++mb) {
                mma16816(d[mb][2 * ntp],     ah[mb][0], ah[mb][1], ah[mb][2], ah[mb][3], h0, h1);
                mma16816(d[mb][2 * ntp + 1], ah[mb][0], ah[mb][1], ah[mb][2], ah[mb][3], h2, h3);
                mma16816(d[mb][2 * ntp],     al[mb][0], al[mb][1], al[mb][2], al[mb][3], h0, h1);
                mma16816(d[mb][2 * ntp + 1], al[mb][0], al[mb][1], al[mb][2], al[mb][3], h2, h3);
                mma16816(d[mb][2 * ntp],     ah[mb][0], ah[mb][1], ah[mb][2], ah[mb][3], l0, l1);
                mma16816(d[mb][2 * ntp + 1], ah[mb][0], ah[mb][1], ah[mb][2], ah[mb][3], l2, l3);
            }
        }
    }
}

__global__ __launch_bounds__(kTHREADS, 1)
void ta_pers(const float* __restrict__ x,
             const float* __restrict__ Wq, const float* __restrict__ bq,
             const float* __restrict__ Wk, const float* __restrict__ bk,
             const float* __restrict__ Wv, const float* __restrict__ bv,
             float* __restrict__ out, int total)
{
    extern __shared__ char smem[];
    const uint32_t sb = s2u(smem);
    float* outst   = (float*)(smem + OUTS);
    float* bias_sm = (float*)(smem + BIAS);
    float* Ssm     = (float*)(smem + SSM);

    const int tid = threadIdx.x, wid = tid >> 5, lane = tid & 31;
    const int l4 = lane & 3, lg = lane >> 2;
    const int p16 = tid & 15;                  // pixel for x IO
    const int tcg = tid >> 4;                  // tc-group (16 groups)
    const int w4  = tcg >> 1;                  // = warp id (cp base)
    const int cta = blockIdx.x;

    // ---- weights hi/lo staged ONCE ---------------------------------------
    for (int i = tid; i < 128 * 64; i += kTHREADS) {
        int n = i >> 6, cp = i & 63;
        const float* src = (n < 64) ? (Wq + n * kC) : (Wk + (n - 64) * kC);
        float2 v = *(const float2*)(src + cp * 2);
        uint32_t hw, lw;
        split2(v.x, v.y, hw, lw);
        *(uint32_t*)(smem + BQK_HI + n * kSA + cp * 4) = hw;
        *(uint32_t*)(smem + BQK_LO + n * kSA + cp * 4) = lw;
    }
    for (int i = tid; i < 128 * 64; i += kTHREADS) {
        int n = i >> 6, cp = i & 63;
        float2 v = *(const float2*)(Wv + n * kC + cp * 2);
        uint32_t hw, lw;
        split2(v.x, v.y, hw, lw);
        *(uint32_t*)(smem + BV_HI + n * kSA + cp * 4) = hw;
        *(uint32_t*)(smem + BV_LO + n * kSA + cp * 4) = lw;
    }
    bias_sm[tid] = (tid < 64) ? bq[tid]
                 : (tid < 128) ? bk[tid - 64] : bv[tid - 128];
    __syncthreads();

    // precomputed A-staging address pieces (per thread)
    const uint32_t m_base = (uint32_t)p16 * 8;          // + t
    const uint32_t xor7   = (uint32_t)(p16 & 7);

    // ======================= persistent tile loop ==========================
    for (int tt = cta; tt < total; tt += kGRID) {
        const size_t tile_off = (size_t)(tt / 576) * (kT * kC * kHW) +
                                (size_t)(tt % 576) * kPIX;

        // ---- x load: thread (p16, tcg), element tc = j*16+tcg ------------
        float xr[64];
        {
            const float* xb = x + tile_off;
#pragma unroll
            for (int j = 0; j < 64; ++j)
                xr[j] = xb[(size_t)(j * 16 + tcg) * kHW + p16];
        }
        // ---- direct A staging: split + pair via shfl + swizzled STS ------
#pragma unroll
        for (int j = 0; j < 64; ++j) {
            int t = j >> 3;
            int cp = (j & 7) * 8 + w4;
            __nv_bfloat16 h = __float2bfloat16(xr[j]);
            float r = xr[j] - __bfloat162float(h);
            __nv_bfloat16 l = __float2bfloat16(r);
            uint32_t pack = ((uint32_t)__bfloat16_as_ushort(h) << 16) |
                            __bfloat16_as_ushort(l);
            uint32_t pp = __shfl_xor_sync(0xffffffffu, pack, 16);
            uint32_t ch = (uint32_t)(cp >> 2);
            uint32_t addr = (m_base + t) * kSA + ((ch ^ xor7) << 4) +
                            (uint32_t)(cp & 3) * 4;
            if (lane < 16) {    // owns c-even: write HI pair
                uint32_t hw = (pack >> 16) | (pp & 0xFFFF0000u);
                *(uint32_t*)(smem + A_HI + addr) = hw;
            } else {            // owns c-odd: write LO pair
                uint32_t lw = (pp & 0xFFFFu) | (pack << 16);
                *(uint32_t*)(smem + A_LO + addr) = lw;
            }
        }
        __syncthreads();

        // ---- GEMMs (warp-specialized) + softmax --------------------------
        const int gw = wid & 3;
        float d[2][16][4];
        if (wid < 4) {
            do_gemm32(sb + A_HI, sb + A_LO, sb + BQK_HI, sb + BQK_LO, lane, gw, d);
#pragma unroll
            for (int mb = 0; mb < 2; ++mb) {
#pragma unroll
                for (int nt = 0; nt < 16; ++nt) {
                    int c = (nt & 7) * 8 + l4 * 2;
                    float b0 = bias_sm[(nt < 8 ? 0 : 64) + c];
                    float b1 = bias_sm[(nt < 8 ? 0 : 64) + c + 1];
                    d[mb][nt][0] += b0; d[mb][nt][1] += b1;
                    d[mb][nt][2] += b0; d[mb][nt][3] += b1;
                }
#pragma unroll
                for (int pi = 0; pi < 2; ++pi) {
                    float sc[8];
#pragma unroll
                    for (int s = 0; s < 8; ++s) {
                        int src = s * 4 + l4;
                        float a = 0.f;
#pragma unroll
                        for (int nt = 0; nt < 8; ++nt)
#pragma unroll
                            for (int j = 0; j < 2; ++j)
                                a += d[mb][nt][pi * 2 + j] *
                                     __shfl_sync(0xffffffffu,
                                                 d[mb][8 + nt][pi * 2 + j], src);
                        a += __shfl_xor_sync(0xffffffffu, a, 1);
                        a += __shfl_xor_sync(0xffffffffu, a, 2);
                        sc[s] = a * 0.125f;         // 1/sqrt(64)
                    }
                    float mx = sc[0];
#pragma unroll
                    for (int s = 1; s < 8; ++s) mx = fmaxf(mx, sc[s]);
                    float sum = 0.f, e[8];
#pragma unroll
                    for (int s = 0; s < 8; ++s) { e[s] = __expf(sc[s] - mx); sum += e[s]; }
                    float inv = 1.f / sum;
                    if (l4 == 0) {
                        int p = gw * 4 + mb * 2 + pi;
#pragma unroll
                        for (int s = 0; s < 8; ++s)
                            Ssm[(p * 8 + lg) * 8 + s] = e[s] * inv;
                    }
                }
            }
        } else {
            do_gemm32(sb + A_HI, sb + A_LO, sb + BV_HI, sb + BV_LO, lane, gw, d);
        }
        __syncthreads();    // all GEMMs done (A dead), Ssm ready

        // ---- V warps: attn@V + bv -> outst (rotated, aliases A) ----------
        if (wid >= 4) {
#pragma unroll
            for (int mb = 0; mb < 2; ++mb) {
                const int p0 = gw * 4 + mb * 2, p1 = p0 + 1;
                float attn0[8], attn1[8];
#pragma unroll
                for (int s = 0; s < 8; ++s) {
                    attn0[s] = Ssm[(p0 * 8 + lg) * 8 + s];
                    attn1[s] = Ssm[(p1 * 8 + lg) * 8 + s];
                }
#pragma unroll
                for (int nt = 0; nt < 16; ++nt)
#pragma unroll
                    for (int j = 0; j < 2; ++j) {
                        int c = nt * 8 + l4 * 2 + j;
                        float o0 = bias_sm[128 + c], o1 = o0;
#pragma unroll
                        for (int s = 0; s < 8; ++s) {
                            int src = s * 4 + l4;
                            o0 += attn0[s] * __shfl_sync(0xffffffffu, d[mb][nt][j], src);
                            o1 += attn1[s] * __shfl_sync(0xffffffffu, d[mb][nt][2 + j], src);
                        }
                        int base = (lg * 128 + c) * 16 + lg * 4;
                        int rot = (c >> 1) & 15;
                        outst[base + ((p0 + rot) & 15)] = o0;
                        outst[base + ((p1 + rot) & 15)] = o1;
                    }
            }
        }
        __syncthreads();

        // ---- coalesced gmem store: out[b,t,e,pix0+p] ---------------------
        {
            float* ob = out + tile_off;
#pragma unroll 4
            for (int it = 0; it < 64; ++it) {
                int q = it * 16 + tcg;          // t*128 + e
                int t = q >> 7, c = q & 127;
                ob[(size_t)q * kHW + p16] =
                    outst[q * 16 + ((p16 + (c >> 1)) & 15) + t * 4];
            }
        }
        __syncthreads();    // protect outst (=A) before next staging
    }
}

extern "C" void kernel_launch(void* const* d_in, const int* in_sizes, int n_in,
                              void* d_out, int out_size)
{
    const float* x  = (const float*)d_in[0];
    const float* Wq = (const float*)d_in[1];
    const float* bq = (const float*)d_in[2];
    const float* Wk = (const float*)d_in[3];
    const float* bk = (const float*)d_in[4];
    const float* Wv = (const float*)d_in[5];
    const float* bv = (const float*)d_in[6];
    float* out = (float*)d_out;

    const int B = in_sizes[0] / (kT * kC * kHW);
    const int total = B * (kHW / kPIX);         // 16-pixel tiles
    cudaFuncSetAttribute(ta_pers, cudaFuncAttributeMaxDynamicSharedMemorySize,
                         kSMEM);
    ta_pers<<<kGRID, kTHREADS, kSMEM>>>(x, Wq, bq, Wk, bk, Wv, bv, out, total);
}

// round 17
// speedup vs baseline: 1.8083x; 1.8083x over previous
#include <cuda_runtime.h>
#include <cuda_fp16.h>
#include <cstdint>
#include <cstddef>

// TemporalAttention — persistent-CTA fp16 mma.sync version.
// 152 CTAs x 256 threads; 8-pixel tiles (m = p*8+t, 64 rows).
// 2-term fp16 split: A (X) staged hi+lo, weights rounded to fp16 once per CTA.
// D = (Ahi + Alo) * Bhi  -> error ~|A||B|*2^-12, aggregate ~3e-4.
// Warps 0-3: QK GEMM + softmax; warps 4-7: V GEMM + attn-mix (concurrent).
// Next tile's x prefetched into registers under current tile's GEMMs.
// R15 bug fixed: OUTS region is 41024 B (max outst index 10251 floats).

namespace {
constexpr int kT = 8, kC = 128, kHW = 9216, kPIX = 8, kTHREADS = 256;
constexpr int kGRID = 152;
constexpr int kSA = 272;                 // row stride in bytes (136 fp16)
// smem byte offsets
constexpr int BQK_HI = 0;                // 128 x 272 (fp16 hi only)
constexpr int BV_HI  = 34816;
constexpr int A_HI   = 69632;            // 64 x 272
constexpr int A_LO   = 87040;
constexpr int OUTS   = 104448;           // out staging, needs 41024 B
constexpr int BIAS   = 145472;           // 256 floats  (OUTS + 41024)
constexpr int SSM    = 146496;           // 8px * 64 floats
constexpr int kSMEM  = 148544;
}

__device__ __forceinline__ uint32_t s2u(const void* p) {
    uint32_t a;
    asm("{ .reg .u64 t; cvta.to.shared.u64 t, %1; cvt.u32.u64 %0, t; }"
        : "=r"(a) : "l"(p));
    return a;
}
__device__ __forceinline__ void ldsm4(uint32_t& r0, uint32_t& r1, uint32_t& r2,
                                      uint32_t& r3, uint32_t addr) {
    asm volatile("ldmatrix.sync.aligned.m8n8.x4.shared.b16 {%0,%1,%2,%3}, [%4];"
                 : "=r"(r0), "=r"(r1), "=r"(r2), "=r"(r3) : "r"(addr));
}
__device__ __forceinline__ void mma16816(float* d, uint32_t a0, uint32_t a1,
                                         uint32_t a2, uint32_t a3,
                                         uint32_t b0, uint32_t b1) {
    asm volatile(
        "mma.sync.aligned.m16n8k16.row.col.f32.f16.f16.f32 "
        "{%0,%1,%2,%3}, {%4,%5,%6,%7}, {%8,%9}, {%0,%1,%2,%3};"
        : "+f"(d[0]), "+f"(d[1]), "+f"(d[2]), "+f"(d[3])
        : "r"(a0), "r"(a1), "r"(a2), "r"(a3), "r"(b0), "r"(b1));
}
__device__ __forceinline__ uint32_t pack_hi2(float v0, float v1) {
    return ((uint32_t)__half_as_ushort(__float2half(v1)) << 16) |
           __half_as_ushort(__float2half(v0));
}

// 16(m: rows gw*16..+15) x 128(n) x 128(k) 2-term GEMM.
// A region chunk-XOR swizzled: 16B chunk ch of row m lives at ch ^ ((m>>3)&7).
// B region linear (row n, 272B stride).
__device__ __forceinline__ void do_gemm(uint32_t aHi, uint32_t aLo,
                                        uint32_t bHi,
                                        int lane, int gw, float d[16][4]) {
#pragma unroll
    for (int nt = 0; nt < 16; ++nt)
#pragma unroll
        for (int r = 0; r < 4; ++r) d[nt][r] = 0.f;

    const int l15 = lane & 15, lh = lane >> 4;
    const int m = gw * 16 + l15;
    const uint32_t rowo = (uint32_t)m * kSA;
    const uint32_t x7 = (uint32_t)((m >> 3) & 7);
    const int bro = (lane & 7) + (((lane >> 4) & 1) * 8);
    const uint32_t bkh = (uint32_t)(((lane >> 3) & 1) * 16);

#pragma unroll
    for (int ks = 0; ks < 8; ++ks) {
        uint32_t ao = rowo + ((((uint32_t)(ks * 2) + lh) ^ x7) << 4);
        uint32_t ah0, ah1, ah2, ah3, al0, al1, al2, al3;
        ldsm4(ah0, ah1, ah2, ah3, aHi + ao);
        ldsm4(al0, al1, al2, al3, aLo + ao);
#pragma unroll
        for (int ntp = 0; ntp < 8; ++ntp) {
            uint32_t bo = (uint32_t)(ntp * 16 + bro) * kSA + ks * 32 + bkh;
            uint32_t b0, b1, b2, b3;
            ldsm4(b0, b1, b2, b3, bHi + bo);
            mma16816(d[2 * ntp],     ah0, ah1, ah2, ah3, b0, b1);
            mma16816(d[2 * ntp + 1], ah0, ah1, ah2, ah3, b2, b3);
            mma16816(d[2 * ntp],     al0, al1, al2, al3, b0, b1);
            mma16816(d[2 * ntp + 1], al0, al1, al2, al3, b2, b3);
        }
    }
}

__global__ __launch_bounds__(kTHREADS, 1)
void ta_pers(const float* __restrict__ x,
             const float* __restrict__ Wq, const float* __restrict__ bq,
             const float* __restrict__ Wk, const float* __restrict__ bk,
             const float* __restrict__ Wv, const float* __restrict__ bv,
             float* __restrict__ out, int total)
{
    extern __shared__ char smem[];
    const uint32_t sb = s2u(smem);
    float* outst   = (float*)(smem + OUTS);
    float* bias_sm = (float*)(smem + BIAS);
    float* Ssm     = (float*)(smem + SSM);

    const int tid = threadIdx.x, wid = tid >> 5, lane = tid & 31;
    const int l4 = lane & 3, lg = lane >> 2;
    const int p8 = tid & 7, tcb = tid >> 3;    // x-IO pixel / tc-group (32)
    const int cta = blockIdx.x;

    // ---- prefetch first tile's x into registers --------------------------
    float xr[32];
    if (cta < total) {
        const float* xb = x + (size_t)(cta / 1152) * (kT * kC * kHW) +
                          (size_t)(cta % 1152) * kPIX;
#pragma unroll
        for (int j = 0; j < 32; ++j)
            xr[j] = xb[(size_t)(j * 32 + tcb) * kHW + p8];
    }

    // ---- weights: fp16 HI only, staged ONCE ------------------------------
    for (int i = tid; i < 128 * 64; i += kTHREADS) {
        int n = i >> 6, cp = i & 63;
        const float* src = (n < 64) ? (Wq + n * kC) : (Wk + (n - 64) * kC);
        float2 v = *(const float2*)(src + cp * 2);
        *(uint32_t*)(smem + BQK_HI + n * kSA + cp * 4) = pack_hi2(v.x, v.y);
    }
    for (int i = tid; i < 128 * 64; i += kTHREADS) {
        int n = i >> 6, cp = i & 63;
        float2 v = *(const float2*)(Wv + n * kC + cp * 2);
        *(uint32_t*)(smem + BV_HI + n * kSA + cp * 4) = pack_hi2(v.x, v.y);
    }
    bias_sm[tid] = (tid < 64) ? bq[tid]
                 : (tid < 128) ? bk[tid - 64] : bv[tid - 128];
    __syncthreads();

    // ======================= persistent tile loop ==========================
    for (int tt = cta; tt < total; tt += kGRID) {
        // ---- direct A staging: fp16 split + shfl pairing + swizzled STS --
        // thread holds x[tc = j*32 + tcb] for pixel p8; pair partner lane^8.
#pragma unroll
        for (int j = 0; j < 32; ++j) {
            int tc = j * 32 + tcb;
            int t = tc >> 7, c = tc & 127;
            __half h = __float2half(xr[j]);
            float r = xr[j] - __half2float(h);
            __half l = __float2half(r);
            uint32_t pack = ((uint32_t)__half_as_ushort(h) << 16) |
                            __half_as_ushort(l);
            uint32_t pp = __shfl_xor_sync(0xffffffffu, pack, 8);
            int cp = c >> 1;
            uint32_t addr = (uint32_t)(p8 * 8 + t) * kSA +
                            ((((uint32_t)cp >> 2) ^ (uint32_t)p8) << 4) +
                            (uint32_t)(cp & 3) * 4;
            if ((tcb & 1) == 0) {   // even c: HI word (hi_c | hi_{c+1}<<16)
                *(uint32_t*)(smem + A_HI + addr) =
                    (pack >> 16) | (pp & 0xFFFF0000u);
            } else {                // odd c: LO word (lo_c | lo_{c+1}<<16)
                *(uint32_t*)(smem + A_LO + addr) =
                    (pp & 0xFFFFu) | (pack << 16);
            }
        }
        // ---- issue next tile's LDGs (retire under this tile's GEMMs) -----
        {
            int nxt = tt + kGRID;
            if (nxt < total) {
                const float* xb = x + (size_t)(nxt / 1152) * (kT * kC * kHW) +
                                  (size_t)(nxt % 1152) * kPIX;
#pragma unroll
                for (int j = 0; j < 32; ++j)
                    xr[j] = xb[(size_t)(j * 32 + tcb) * kHW + p8];
            }
        }
        __syncthreads();

        // ---- GEMMs (warp-specialized) + softmax --------------------------
        const int gw = wid & 3;
        float d[16][4];
        if (wid < 4) {
            do_gemm(sb + A_HI, sb + A_LO, sb + BQK_HI, lane, gw, d);
            // bias in-place: nt<8 -> Q (+bq), nt>=8 -> K (+bk)
#pragma unroll
            for (int nt = 0; nt < 16; ++nt) {
                int c = (nt & 7) * 8 + l4 * 2;
                float b0 = bias_sm[(nt < 8 ? 0 : 64) + c];
                float b1 = bias_sm[(nt < 8 ? 0 : 64) + c + 1];
                d[nt][0] += b0; d[nt][1] += b1;
                d[nt][2] += b0; d[nt][3] += b1;
            }
#pragma unroll
            for (int pi = 0; pi < 2; ++pi) {
                float sc[8];
#pragma unroll
                for (int s = 0; s < 8; ++s) {
                    int src = s * 4 + l4;
                    float a = 0.f;
#pragma unroll
                    for (int nt = 0; nt < 8; ++nt)
#pragma unroll
                        for (int j = 0; j < 2; ++j)
                            a += d[nt][pi * 2 + j] *
                                 __shfl_sync(0xffffffffu, d[8 + nt][pi * 2 + j], src);
                    a += __shfl_xor_sync(0xffffffffu, a, 1);
                    a += __shfl_xor_sync(0xffffffffu, a, 2);
                    sc[s] = a * 0.125f;           // 1/sqrt(64)
                }
                float mx = sc[0];
#pragma unroll
                for (int s = 1; s < 8; ++s) mx = fmaxf(mx, sc[s]);
                float sum = 0.f, e[8];
#pragma unroll
                for (int s = 0; s < 8; ++s) { e[s] = __expf(sc[s] - mx); sum += e[s]; }
                float inv = 1.f / sum;
                if (l4 == 0) {
                    int p = gw * 2 + pi;
#pragma unroll
                    for (int s = 0; s < 8; ++s)
                        Ssm[(p * 8 + lg) * 8 + s] = e[s] * inv;
                }
            }
        } else {
            do_gemm(sb + A_HI, sb + A_LO, sb + BV_HI, lane, gw, d);
        }
        __syncthreads();    // all GEMMs done (A reusable), Ssm ready

        // ---- V warps: attn@V + bv -> outst (rotated for coalesced IO) ----
        if (wid >= 4) {
            const int p0 = gw * 2, p1 = p0 + 1;
            float attn0[8], attn1[8];
#pragma unroll
            for (int s = 0; s < 8; ++s) {
                attn0[s] = Ssm[(p0 * 8 + lg) * 8 + s];
                attn1[s] = Ssm[(p1 * 8 + lg) * 8 + s];
            }
#pragma unroll
            for (int nt = 0; nt < 16; ++nt)
#pragma unroll
                for (int j = 0; j < 2; ++j) {
                    int c = nt * 8 + l4 * 2 + j;
                    float o0 = bias_sm[128 + c], o1 = o0;
#pragma unroll
                    for (int s = 0; s < 8; ++s) {
                        int src = s * 4 + l4;
                        o0 += attn0[s] * __shfl_sync(0xffffffffu, d[nt][j], src);
                        o1 += attn1[s] * __shfl_sync(0xffffffffu, d[nt][2 + j], src);
                    }
                    int rot = (c >> 1) & 7;
                    int base = (lg * 128 + c) * 10 + lg * 2;
                    outst[base + ((p0 + rot) & 7)] = o0;
                    outst[base + ((p1 + rot) & 7)] = o1;
                }
        }
        __syncthreads();

        // ---- coalesced gmem store: out[b,t,e,pix0+p] ---------------------
        {
            float* ob = out + (size_t)(tt / 1152) * (kT * kC * kHW) +
                        (size_t)(tt % 1152) * kPIX;
#pragma unroll 4
            for (int it2 = 0; it2 < 32; ++it2) {
                int q = it2 * 32 + tcb;           // t*128 + e
                int t = q >> 7, c = q & 127, rot = (c >> 1) & 7;
                ob[(size_t)q * kHW + p8] =
                    outst[q * 10 + t * 2 + ((p8 + rot) & 7)];
            }
        }
        __syncthreads();    // protect outst before next staging
    }
}

extern "C" void kernel_launch(void* const* d_in, const int* in_sizes, int n_in,
                              void* d_out, int out_size)
{
    const float* x  = (const float*)d_in[0];
    const float* Wq = (const float*)d_in[1];
    const float* bq = (const float*)d_in[2];
    const float* Wk = (const float*)d_in[3];
    const float* bk = (const float*)d_in[4];
    const float* Wv = (const float*)d_in[5];
    const float* bv = (const float*)d_in[6];
    float* out = (float*)d_out;

    const int B = in_sizes[0] / (kT * kC * kHW);
    const int total = B * (kHW / kPIX);           // 8-pixel tiles
    cudaFuncSetAttribute(ta_pers, cudaFuncAttributeMaxDynamicSharedMemorySize,
                         kSMEM);
    ta_pers<<<kGRID, kTHREADS, kSMEM>>>(x, Wq, bq, Wk, bk, Wv, bv, out, total);
}